// round 12
// baseline (speedup 1.0000x reference)
#include <cuda_runtime.h>
#include <cuda_bf16.h>
#include <cstdint>

// BatchDepthwiseCrossCorrelation via warp TF32 MMA (m16n8k8, single pass, RNA rounding).
//   x:         [8, 256, 64, 64]  f32
//   templates: [8, 8, 256, 7, 7] f32
//   out:       [8, 8, 256, 64, 64] f32
// Per channel c: out[p, nt] = sum_tap patch[p, tap] * t[nt, tap]
// MMA tile: rows 0-7 = pixels (ty, x0+r), rows 8-15 = (ty+1, x0+r); cols = nt (8);
// one MMA per ky (k = 8 kx taps, kx=7 zero), ky = 0..6 -> 7 MMAs per tile.

#define BSNC   2048
#define HI     64
#define WI     64
#define PLANE  (HI*WI)
#define PAD    3
#define NT     8
#define QROWS  16                 // output rows per CTA (quarter plane)
#define SROWS  23                 // padded plane rows staged
#define SPW    72                 // pair-plane row pitch (float2)
#define NTHREADS 128

__device__ __forceinline__ void mma_tf32(float& d0, float& d1, float& d2, float& d3,
                                         uint32_t a0, uint32_t a1, uint32_t a2, uint32_t a3,
                                         uint32_t b0, uint32_t b1) {
    asm volatile(
        "mma.sync.aligned.m16n8k8.row.col.f32.tf32.tf32.f32 "
        "{%0,%1,%2,%3}, {%4,%5,%6,%7}, {%8,%9}, {%0,%1,%2,%3};"
        : "+f"(d0), "+f"(d1), "+f"(d2), "+f"(d3)
        : "r"(a0), "r"(a1), "r"(a2), "r"(a3), "r"(b0), "r"(b1));
}

__device__ __forceinline__ uint32_t tf32_rna(float v) {
    uint32_t r;
    asm("cvt.rna.tf32.f32 %0, %1;" : "=r"(r) : "f"(v));
    return r;
}

__global__ __launch_bounds__(NTHREADS, 8)
void dwxcorr_tf32_kernel(const float* __restrict__ x,
                         const float* __restrict__ tm,
                         float* __restrict__ out)
{
    __shared__ uint2 s_pair[SROWS][SPW];                // {tf32(x at xf), tf32(x at xf+4)}
    __shared__ __align__(16) uint32_t s_tmpl[NT][64];   // tf32 templates, tap = ky*8+kx

    const int c   = blockIdx.x >> 2;            // fused (b, ch) channel
    const int y0  = (blockIdx.x & 3) * QROWS;   // top output row of this quarter
    const int tid = threadIdx.x;
    const int wid = tid >> 5;
    const int lane = tid & 31;
    const int q = lane & 3;                     // tid-in-group: k index (A cols q, q+4)
    const int r = lane >> 2;                    // group id: A row / B col (nt)

    // ---- Prologue: zero-fill ----
    for (int i = tid; i < SROWS * SPW; i += NTHREADS)
        ((uint2*)s_pair)[i] = make_uint2(0u, 0u);
    for (int i = tid; i < NT * 64; i += NTHREADS) ((uint32_t*)s_tmpl)[i] = 0u;
    __syncthreads();

    // Fill valid rows: padded row a holds plane row gy = y0 + a - 3.
    {
        const int a0 = (y0 == 0) ? PAD : 0;
        int a1 = 66 - y0; if (a1 > SROWS - 1) a1 = SROWS - 1;
        const int nrows = a1 - a0 + 1;
        const float* xc = x + (size_t)c * PLANE;
        for (int i = tid; i < nrows * 71; i += NTHREADS) {
            int rr = i / 71;
            int cc = i - rr * 71;
            int gy = y0 + (a0 + rr) - PAD;
            const float* row = xc + (size_t)gy * WI;
            int gx0 = cc - PAD;            // pair element 0: padded col cc
            int gx1 = cc + 1;              // pair element 1: padded col cc+4 -> gx = cc+1
            uint32_t v0 = (gx0 >= 0 && gx0 < WI) ? tf32_rna(row[gx0]) : 0u;
            uint32_t v1 = (gx1 < WI) ? tf32_rna(row[gx1]) : 0u;
            s_pair[a0 + rr][cc] = make_uint2(v0, v1);
        }
    }
    // Templates: scatter taps into [nt][ky*8+kx] (kx=7, ky=7 stay zero), TF32-rounded.
    for (int i = tid; i < NT * 49; i += NTHREADS) {
        int nt = i / 49, tap = i - nt * 49;
        int ky = tap / 7, kx = tap - ky * 7;
        s_tmpl[nt][ky * 8 + kx] = tf32_rna(tm[((size_t)nt * BSNC + c) * 49 + tap]);
    }
    __syncthreads();

    // ---- B fragments: b0[ky] = t[nt=r][ky*8+q], b1[ky] = t[nt=r][ky*8+q+4] ----
    uint32_t b0[7], b1[7];
    #pragma unroll
    for (int ky = 0; ky < 7; ky++) {
        b0[ky] = s_tmpl[r][ky * 8 + q];
        b1[ky] = s_tmpl[r][ky * 8 + q + 4];
    }

    const size_t planeN = (size_t)BSNC * PLANE;

    // ---- Mainloop: 2 x-strips per warp, 8 y-pair tiles per strip ----
    #pragma unroll
    for (int sidx = 0; sidx < 2; sidx++) {
        const int x0 = (wid + 4 * sidx) * 8;
        const int xf = x0 + r + q;              // fixed fragment x (pair covers xf, xf+4)
        float* obase = out + (size_t)c * PLANE + (size_t)y0 * WI
                     + (size_t)(x0 + r) + (size_t)(2 * q) * planeN;

        uint2 W[SROWS];                         // constant-indexed, live range 8 rows

        #pragma unroll
        for (int a = 0; a < 8; a++) W[a] = s_pair[a][xf];

        #pragma unroll
        for (int typ = 0; typ < 8; typ++) {
            const int ty = 2 * typ;
            float d0 = 0.f, d1 = 0.f, d2 = 0.f, d3 = 0.f;

            #pragma unroll
            for (int ky = 0; ky < 7; ky++) {
                // a0=(ty,xf) a1=(ty+1,xf) a2=(ty,xf+4) a3=(ty+1,xf+4), at plane row +ky
                mma_tf32(d0, d1, d2, d3,
                         W[ty + ky].x, W[ty + ky + 1].x,
                         W[ty + ky].y, W[ty + ky + 1].y,
                         b0[ky], b1[ky]);
            }

            float* ob = obase + (size_t)ty * WI;
            ob[0]           = d0;   // (pixel ty,   nt 2q)
            ob[planeN]      = d1;   // (pixel ty,   nt 2q+1)
            ob[WI]          = d2;   // (pixel ty+1, nt 2q)
            ob[planeN + WI] = d3;   // (pixel ty+1, nt 2q+1)

            if (typ < 7) {
                W[ty + 8] = s_pair[ty + 8][xf];
                W[ty + 9] = s_pair[ty + 9][xf];
            }
        }
    }
}

extern "C" void kernel_launch(void* const* d_in, const int* in_sizes, int n_in,
                              void* d_out, int out_size)
{
    const float* x  = (const float*)d_in[0];
    const float* tm = (const float*)d_in[1];
    float* out      = (float*)d_out;
    dwxcorr_tf32_kernel<<<BSNC * 4, NTHREADS>>>(x, tm, out);
}

// round 14
// speedup vs baseline: 1.0102x; 1.0102x over previous
#include <cuda_runtime.h>
#include <cuda_bf16.h>
#include <cstdint>

// BatchDepthwiseCrossCorrelation via warp TF32 MMA (m16n8k8, single pass, RNA rounding),
// half-plane CTAs, split accumulator chains.
//   x:         [8, 256, 64, 64]  f32
//   templates: [8, 8, 256, 7, 7] f32
//   out:       [8, 8, 256, 64, 64] f32
// Per channel c: out[p, nt] = sum_tap patch[p, tap] * t[nt, tap]
// MMA tile: rows 0-7 = pixels (ty, x0+r), rows 8-15 = (ty+1, x0+r); cols = nt (8);
// one MMA per ky (k = 8 kx taps, kx=7 zero), ky = 0..6 -> 7 MMAs per tile, 2 chains.

#define BSNC   2048
#define HI     64
#define WI     64
#define PLANE  (HI*WI)
#define PAD    3
#define NT     8
#define HROWS  32                 // output rows per CTA (half plane)
#define SROWS  38                 // padded plane rows staged (31+6+1)
#define SPW    72                 // pair-plane row pitch (uint2)
#define NTHREADS 256

__device__ __forceinline__ void mma_tf32(float& d0, float& d1, float& d2, float& d3,
                                         uint32_t a0, uint32_t a1, uint32_t a2, uint32_t a3,
                                         uint32_t b0, uint32_t b1) {
    asm volatile(
        "mma.sync.aligned.m16n8k8.row.col.f32.tf32.tf32.f32 "
        "{%0,%1,%2,%3}, {%4,%5,%6,%7}, {%8,%9}, {%0,%1,%2,%3};"
        : "+f"(d0), "+f"(d1), "+f"(d2), "+f"(d3)
        : "r"(a0), "r"(a1), "r"(a2), "r"(a3), "r"(b0), "r"(b1));
}

__device__ __forceinline__ uint32_t tf32_rna(float v) {
    uint32_t r;
    asm("cvt.rna.tf32.f32 %0, %1;" : "=r"(r) : "f"(v));
    return r;
}

__global__ __launch_bounds__(NTHREADS, 4)
void dwxcorr_tf32_kernel(const float* __restrict__ x,
                         const float* __restrict__ tm,
                         float* __restrict__ out)
{
    __shared__ uint2 s_pair[SROWS][SPW];                // {tf32 x(cc-3), tf32 x(cc+1)}
    __shared__ __align__(16) uint32_t s_tmpl[NT][64];   // tf32 templates, tap = ky*8+kx

    const int c   = blockIdx.x >> 1;            // fused (b, ch) channel
    const int y0  = (blockIdx.x & 1) * HROWS;   // top output row of this half
    const int tid = threadIdx.x;
    const int wid = tid >> 5;
    const int lane = tid & 31;
    const int q = lane & 3;                     // k index (A cols q, q+4); nt pair 2q
    const int r = lane >> 2;                    // A row / B col (nt)

    // ---- Prologue: single predicated pass over the padded pair-plane ----
    {
        const float* xc = x + (size_t)c * PLANE;
        for (int i = tid; i < SROWS * SPW; i += NTHREADS) {
            int a  = i / SPW;
            int cc = i - a * SPW;
            int gy = y0 + a - PAD;
            bool yok = (gy >= 0) && (gy < HI);
            const float* row = xc + (size_t)gy * WI;
            int gx0 = cc - PAD;
            int gx1 = cc + 1;
            uint32_t v0 = (yok && gx0 >= 0 && gx0 < WI) ? tf32_rna(row[gx0]) : 0u;
            uint32_t v1 = (yok && gx1 < WI) ? tf32_rna(row[gx1]) : 0u;
            s_pair[a][cc] = make_uint2(v0, v1);
        }
    }
    // Templates: zero then scatter taps into [nt][ky*8+kx] (kx=7, ky=7 stay zero).
    for (int i = tid; i < NT * 64; i += NTHREADS) ((uint32_t*)s_tmpl)[i] = 0u;
    __syncthreads();   // s_tmpl zeros visible before scatter (different threads touch same rows)
    for (int i = tid; i < NT * 49; i += NTHREADS) {
        int nt = i / 49, tap = i - nt * 49;
        int ky = tap / 7, kx = tap - ky * 7;
        s_tmpl[nt][ky * 8 + kx] = tf32_rna(tm[((size_t)nt * BSNC + c) * 49 + tap]);
    }
    __syncthreads();

    // ---- B fragments: b0[ky] = t[nt=r][ky*8+q], b1[ky] = t[nt=r][ky*8+q+4] ----
    uint32_t b0[7], b1[7];
    #pragma unroll
    for (int ky = 0; ky < 7; ky++) {
        b0[ky] = s_tmpl[r][ky * 8 + q];
        b1[ky] = s_tmpl[r][ky * 8 + q + 4];
    }

    const size_t planeN = (size_t)BSNC * PLANE;

    // ---- Mainloop: one 8-wide x-strip per warp, 16 y-pair tiles ----
    const int x0 = wid << 3;
    const int xf = x0 + r + q;                  // fixed fragment x (pair covers xf, xf+4)
    float* obase = out + (size_t)c * PLANE + (size_t)y0 * WI
                 + (size_t)(x0 + r) + (size_t)(2 * q) * planeN;

    uint2 W[SROWS];                             // constant-indexed, live range ~10 rows

    #pragma unroll
    for (int a = 0; a < 8; a++) W[a] = s_pair[a][xf];

    #pragma unroll
    for (int typ = 0; typ < 16; typ++) {
        const int ty = 2 * typ;
        // Two independent accumulation chains (ky 0-3 and 4-6), interleaved.
        float e0 = 0.f, e1 = 0.f, e2 = 0.f, e3 = 0.f;
        float f0 = 0.f, f1 = 0.f, f2 = 0.f, f3 = 0.f;

        mma_tf32(e0, e1, e2, e3, W[ty+0].x, W[ty+1].x, W[ty+0].y, W[ty+1].y, b0[0], b1[0]);
        mma_tf32(f0, f1, f2, f3, W[ty+4].x, W[ty+5].x, W[ty+4].y, W[ty+5].y, b0[4], b1[4]);
        mma_tf32(e0, e1, e2, e3, W[ty+1].x, W[ty+2].x, W[ty+1].y, W[ty+2].y, b0[1], b1[1]);
        mma_tf32(f0, f1, f2, f3, W[ty+5].x, W[ty+6].x, W[ty+5].y, W[ty+6].y, b0[5], b1[5]);
        mma_tf32(e0, e1, e2, e3, W[ty+2].x, W[ty+3].x, W[ty+2].y, W[ty+3].y, b0[2], b1[2]);
        mma_tf32(f0, f1, f2, f3, W[ty+6].x, W[ty+7].x, W[ty+6].y, W[ty+7].y, b0[6], b1[6]);
        mma_tf32(e0, e1, e2, e3, W[ty+3].x, W[ty+4].x, W[ty+3].y, W[ty+4].y, b0[3], b1[3]);

        float* ob = obase + (size_t)ty * WI;
        ob[0]           = e0 + f0;   // (pixel ty,   nt 2q)
        ob[planeN]      = e1 + f1;   // (pixel ty,   nt 2q+1)
        ob[WI]          = e2 + f2;   // (pixel ty+1, nt 2q)
        ob[planeN + WI] = e3 + f3;   // (pixel ty+1, nt 2q+1)

        if (typ < 15) {
            W[ty + 8] = s_pair[ty + 8][xf];
            W[ty + 9] = s_pair[ty + 9][xf];
        }
    }
}

extern "C" void kernel_launch(void* const* d_in, const int* in_sizes, int n_in,
                              void* d_out, int out_size)
{
    const float* x  = (const float*)d_in[0];
    const float* tm = (const float*)d_in[1];
    float* out      = (float*)d_out;
    dwxcorr_tf32_kernel<<<BSNC * 2, NTHREADS>>>(x, tm, out);
}